// round 8
// baseline (speedup 1.0000x reference)
#include <cuda_runtime.h>
#include <cstdint>
#include <math.h>

#define Hdim 2048
#define Bdim 16
#define Tdim 1024
#define NIN 8
#define NOUT 8
#define TUNED 10
#define NCTA 128
#define RPC 16
#define NTH 256
#define KC 512
#define NCH 4
#define DTC 0.001f
#define BETAC 1.5f
#define PAD 32

typedef unsigned long long u64;

__device__ float g_Wm[Hdim * Hdim];
__device__ float g_v[2][Bdim * Hdim];
__device__ float g_zt[Tdim * NCTA * 128];
__device__ float g_zp0[NCTA * 128];
__device__ unsigned g_wcnt[NCH * PAD];
__device__ unsigned g_zcnt[PAD];
__device__ int g_zflag;

__device__ __forceinline__ void cp16(float* d, const float* s) {
    unsigned ds = (unsigned)__cvta_generic_to_shared(d);
    asm volatile("cp.async.cg.shared.global [%0],[%1],16;" ::"r"(ds), "l"(s));
}
__device__ __forceinline__ unsigned ldrelax(const unsigned* p) {
    unsigned v;
    asm volatile("ld.relaxed.gpu.global.u32 %0,[%1];" : "=r"(v) : "l"(p));
    return v;
}
__device__ __forceinline__ unsigned ldacq(const unsigned* p) {
    unsigned v;
    asm volatile("ld.acquire.gpu.global.u32 %0,[%1];" : "=r"(v) : "l"(p));
    return v;
}
__device__ __forceinline__ void fence_gpu() {
    asm volatile("fence.acq_rel.gpu;" ::: "memory");
}
__device__ __forceinline__ void red_add(unsigned* p) {
    asm volatile("red.relaxed.gpu.global.add.u32 [%0],1;" ::"l"(p) : "memory");
}
__device__ __forceinline__ void stcs(float* p, float v) {
    asm volatile("st.global.cs.f32 [%0],%1;" ::"l"(p), "f"(v));
}
__device__ __forceinline__ unsigned smaddr(const void* p) {
    return (unsigned)__cvta_generic_to_shared(p);
}
__device__ __forceinline__ unsigned ld_flag(unsigned a) {
    unsigned v;
    asm volatile("ld.acquire.cta.shared.u32 %0,[%1];" : "=r"(v) : "r"(a));
    return v;
}
__device__ __forceinline__ void st_flag(unsigned a, unsigned v) {
    asm volatile("st.release.cta.shared.u32 [%0],%1;" ::"r"(a), "r"(v));
}
__device__ __forceinline__ u64 fma2(u64 a, u64 b, u64 c) {
    u64 d;
    asm("fma.rn.f32x2 %0,%1,%2,%3;" : "=l"(d) : "l"(a), "l"(b), "l"(c));
    return d;
}
__device__ __forceinline__ float unpack_sum(u64 v) {
    float lo, hi;
    asm("mov.b64 {%0,%1},%2;" : "=f"(lo), "=f"(hi) : "l"(v));
    return lo + hi;
}
__device__ __forceinline__ float my_tanh(float x) {
    float e;
    asm("ex2.approx.f32 %0, %1;" : "=f"(e) : "f"(fabsf(x) * 2.8853900817779268f));
    float y = e + 1.0f;
    float r0;
    asm("rcp.approx.f32 %0, %1;" : "=f"(r0) : "f"(y));
    r0 = r0 * fmaf(-y, r0, 2.0f);
    float res = fmaf(-2.0f, r0, 1.0f);
    return copysignf(res, x);
}
__device__ __forceinline__ float merge32(float* a, int l) {
#pragma unroll
    for (int k = 0; k < 5; k++) {
        const int m = 1 << k;
        const bool s = (l >> k) & 1;
#pragma unroll
        for (int i = 0; i < (32 >> (k + 1)); i++) {
            float A = a[2 * i], B = a[2 * i + 1];
            float keep = s ? B : A;
            float send = s ? A : B;
            a[i] = keep + __shfl_xor_sync(0xffffffffu, send, m);
        }
    }
    return a[0];
}

__global__ void reset_counters() {
    int i = threadIdx.x;
    if (i < NCH * PAD) g_wcnt[i] = 0u;
    if (i < PAD) g_zcnt[i] = 0u;
    if (i == 0) g_zflag = 0;
}
__global__ void scan_wzh(const float* __restrict__ wzh) {
    int i = blockIdx.x * 256 + threadIdx.x;
    if (i < Hdim * NOUT && wzh[i] != 0.0f) g_zflag = 1;
}
__global__ void build_wm(const float* __restrict__ wt, const float* __restrict__ wf,
                         const float* __restrict__ mk) {
    int idx = blockIdx.x * 256 + threadIdx.x;
    if (idx < Hdim * Hdim) {
        int j = idx >> 11, k = idx & (Hdim - 1);
        float w = (k < TUNED) ? wt[j * TUNED + k] : wf[j * (Hdim - TUNED) + (k - TUNED)];
        g_Wm[idx] = mk[idx] * w;
    }
}
__global__ void zred(float* __restrict__ out_z) {
    int idx = blockIdx.x * 256 + threadIdx.x;
    int t = idx >> 7, bo = idx & 127;
    const float* p = g_zt + (size_t)t * (NCTA * 128) + bo;
    float s = 0.f;
#pragma unroll 8
    for (int c = 0; c < NCTA; c++) s += __ldcg(p + c * 128);
    out_z[((size_t)(bo >> 3) * Tdim + t) * NOUT + (bo & 7)] = s;
}

// full-CTA prefetch (256 threads, 8 segs each)
__device__ __forceinline__ void prefetch(float* sV, const float* vsrc, int slot, int c, int tid) {
    float* dst = sV + slot * (Bdim * KC);
    const float* src = vsrc + c * KC;
#pragma unroll
    for (int u = 0; u < 8; u++) {
        int seg = u * NTH + tid;
        int b = seg >> 7;
        int f = (seg & 127) << 2;
        cp16(dst + b * KC + f, src + (size_t)b * Hdim + f);
    }
    asm volatile("cp.async.commit_group;" ::: "memory");
}
// half-CTA prefetch (kg1's 128 threads, 16 segs each)
__device__ __forceinline__ void prefetch128(float* sV, const float* vsrc, int slot, int c, int t128) {
    float* dst = sV + slot * (Bdim * KC);
    const float* src = vsrc + c * KC;
#pragma unroll
    for (int u = 0; u < 16; u++) {
        int seg = u * 128 + t128;
        int b = seg >> 7;
        int f = (seg & 127) << 2;
        cp16(dst + b * KC + f, src + (size_t)b * Hdim + f);
    }
    asm volatile("cp.async.commit_group;" ::: "memory");
}

__device__ __forceinline__ void chunk_fma(const float* sWm, const float* sV, u64* acc,
                                          int jbase, int bbase, int kgo, int l,
                                          int c, int slot) {
    const float* Wp = sWm + jbase * Hdim + c * KC + kgo + (l << 2);
    const float* Vp = sV + slot * (Bdim * KC) + bbase * KC + kgo + (l << 2);
#pragma unroll
    for (int it = 0; it < 2; it++) {
        ulonglong2 wv[8], vv[8];
#pragma unroll
        for (int rr = 0; rr < 8; rr++)
            wv[rr] = *(const ulonglong2*)(Wp + rr * Hdim + it * 128);
#pragma unroll
        for (int q = 0; q < 8; q++)
            vv[q] = *(const ulonglong2*)(Vp + q * KC + it * 128);
#pragma unroll
        for (int rr = 0; rr < 8; rr++)
#pragma unroll
            for (int q = 0; q < 8; q++) {
                u64 A = acc[rr * 8 + q];
                A = fma2(wv[rr].x, vv[q].x, A);
                A = fma2(wv[rr].y, vv[q].y, A);
                acc[rr * 8 + q] = A;
            }
    }
}

// boundary: smem flag first, live L2 poll as fallback (also refreshes flag)
__device__ __forceinline__ void flag_poll(unsigned fa, const unsigned* cnt,
                                          unsigned tgt, unsigned stamp, int l) {
    if (ld_flag(fa) < stamp) {
        if (l == 0) {
            while (ldrelax(cnt) < tgt) {}
            while (ldacq(cnt) < tgt) {}
            st_flag(fa, stamp);
        }
        __syncwarp();
    }
}

__global__ __launch_bounds__(NTH, 1) void rnn_persist(
    const float* __restrict__ x, const float* __restrict__ h0,
    const float* __restrict__ Wih, const float* __restrict__ Whz,
    const float* __restrict__ Wzh, const float* __restrict__ tau,
    float* __restrict__ out) {

    extern __shared__ float sm[];
    float* sWm = sm;              // 32768
    float* sV  = sm + 32768;      // 16384
    float* sHT = sm + 49152;      // 256  [j*16+b]
    float* sZ  = sm + 49408;      // 128  (zf fallback)
    float* sX  = sm + 49536;      // 256  double buffered [buf][b*8+i]
    float* sWi = sm + 49792;      // 128
    float* sWz = sm + 49920;      // 128
    float* sWo = sm + 50048;      // 128  [o*16+j]
    float* sTa = sm + 50176;      // 16
    float* sP  = sm + 50192;      // 256  (kg1 partials)
    unsigned* sFlag = (unsigned*)(sm + 50448); // 4

    const int tid = threadIdx.x;
    const int cta = blockIdx.x;
    const int l = tid & 31, w = tid >> 5;
    const int rg = w & 1, bg = (w >> 1) & 1, kg = w >> 2;
    const int jbase = rg * 8, bbase = bg * 8, kgo = kg * 256;
    const int jrow = cta * RPC;
    const int myg = cta >> 5;
    const int zf = g_zflag;
    // cell ownership (meaningful for kg==0, i.e. tid<128): 2 cells per thread
    const int jA = jbase + (l >> 3);
    const int bA = bbase + (l & 7);
    const int cellA = jA * 16 + bA;

    float* out_h = out + (size_t)Bdim * Tdim * NOUT;
    float* out_r = out_h + (size_t)Bdim * Tdim * Hdim;

    const int c0 = myg, c1 = (myg + 1) & 3, c2 = (myg + 2) & 3, c3 = (myg + 3) & 3;
    const unsigned* pc0 = &g_wcnt[c0 * PAD];
    const unsigned* pc1 = &g_wcnt[c1 * PAD];
    const unsigned* pc2 = &g_wcnt[c2 * PAD];
    const unsigned* pc3 = &g_wcnt[c3 * PAD];
    const unsigned fa0 = smaddr(&sFlag[c0]);
    const unsigned fa1 = smaddr(&sFlag[c1]);
    const unsigned fa2 = smaddr(&sFlag[c2]);
    const unsigned fa3 = smaddr(&sFlag[c3]);

    // ---- one-time loads ----
    {
        const float4* src = (const float4*)(g_Wm + (size_t)jrow * Hdim);
        float4* dst = (float4*)sWm;
#pragma unroll 8
        for (int i = tid; i < RPC * Hdim / 4; i += NTH) dst[i] = src[i];
    }
    if (tid < 128) {
        int jj = tid >> 3, ii = tid & 7;
        sWi[tid] = Wih[(jrow + jj) * NIN + ii];
        sWz[tid] = Wzh[(jrow + jj) * NOUT + ii];
        int oo = tid >> 4, j2 = tid & 15;
        sWo[tid] = Whz[oo * Hdim + jrow + j2];
    }
    if (tid < RPC) sTa[tid] = tau[jrow + tid];
    if (tid < 4) sFlag[tid] = 0u;
    __syncthreads();

    // ---- init state: kg0 threads own 2 cells each ----
    float hA = 0.f, rA = 1.0f, hTA = 0.f, itauA = 1.0f;
    float hB = 0.f, rB = 1.0f, hTB = 0.f, itauB = 1.0f;
    if (tid < 128) {
        itauA = 1.0f / sTa[jA];
        itauB = 1.0f / sTa[jA + 4];
        hA = h0[(size_t)bA * Hdim + jrow + jA];
        hB = h0[(size_t)bA * Hdim + jrow + jA + 4];
        hTA = my_tanh(hA);
        hTB = my_tanh(hB);
        __stcg(&g_v[0][bA * Hdim + jrow + jA], hTA);
        __stcg(&g_v[0][bA * Hdim + jrow + jA + 4], hTB);
        sHT[cellA] = hTA;
        sHT[cellA + 64] = hTB;
    }
    __syncthreads();
    if (zf && tid < 128) {
        int bb2 = tid >> 3, oo = tid & 7;
        float s = 0.f;
#pragma unroll
        for (int j2 = 0; j2 < RPC; j2++) s = fmaf(sHT[j2 * 16 + bb2], sWo[oo * 16 + j2], s);
        __stcg(&g_zp0[cta * 128 + tid], s);
    }
    __syncthreads();
    if (tid == 0) {
        fence_gpu();
        red_add(&g_wcnt[myg * PAD]);
        if (zf) red_add(&g_zcnt[0]);
    }

    // ---- prologue: warp4 sets flags for t=0; kg1 prefetch c0 + x(0) ----
    if (w == 4) {
        const unsigned* cp = &g_wcnt[((myg + l) & 3) * PAD];
        bool pass = (l >= 4);
        unsigned ball;
        do {
            if (l < 4 && !pass) pass = (ldrelax(cp) >= 32u);
            ball = __ballot_sync(0xffffffffu, pass);
        } while (!(ball & 1u));
        if (l < 4 && pass) {
            while (ldacq(cp) < 32u) {}
            st_flag(smaddr(&sFlag[(myg + l) & 3]), 1u);
        }
        __syncwarp();
    }
    if (tid >= 128) {
        while (ld_flag(fa0) < 1u) {}
        prefetch128(sV, g_v[0], 0, c0, tid - 128);
        int t128 = tid - 128;
        sX[t128] = x[((size_t)(t128 >> 3) * Tdim + 0) * NIN + (t128 & 7)];
    }

    // ---- time loop ----
    for (int t = 0; t < Tdim; t++) {
        const int cb = t & 1, nb = cb ^ 1;
        const float* vsrc = g_v[cb];
        const unsigned tgt = 32u * (unsigned)(t + 1);
        const unsigned stamp = (unsigned)(t + 1);
        const float* sXc = sX + cb * 128;

        if (zf) {
            if (tid == 0) {
                unsigned zt_ = 128u * (unsigned)(t + 1);
                while (ldrelax(&g_zcnt[0]) < zt_) {}
                while (ldacq(&g_zcnt[0]) < zt_) {}
            }
            __syncthreads();
            if (tid < 128) {
                const float* zp = (t == 0) ? (g_zp0 + tid)
                                           : (g_zt + (size_t)(t - 1) * (NCTA * 128) + tid);
                float s = 0.f;
#pragma unroll 8
                for (int q = 0; q < NCTA; q++) s += __ldcg(zp + q * 128);
                sZ[tid] = s;
            }
        }

        u64 acc[64];
#pragma unroll
        for (int i = 0; i < 64; i++) acc[i] = 0ull;

        // iter 0
        asm volatile("cp.async.wait_group 0;" ::: "memory");
        __syncthreads();
        flag_poll(fa1, pc1, tgt, stamp, l);
        prefetch(sV, vsrc, 1, c1, tid);
        chunk_fma(sWm, sV, acc, jbase, bbase, kgo, l, c0, 0);
        // iter 1
        asm volatile("cp.async.wait_group 0;" ::: "memory");
        __syncthreads();
        flag_poll(fa2, pc2, tgt, stamp, l);
        prefetch(sV, vsrc, 0, c2, tid);
        chunk_fma(sWm, sV, acc, jbase, bbase, kgo, l, c1, 1);
        // iter 2
        asm volatile("cp.async.wait_group 0;" ::: "memory");
        __syncthreads();
        flag_poll(fa3, pc3, tgt, stamp, l);
        prefetch(sV, vsrc, 1, c3, tid);
        chunk_fma(sWm, sV, acc, jbase, bbase, kgo, l, c2, 0);
        // iter 3
        asm volatile("cp.async.wait_group 0;" ::: "memory");
        __syncthreads();
        chunk_fma(sWm, sV, acc, jbase, bbase, kgo, l, c3, 1);

        // ---- reduce ----
        float recA, recB;
        {
            float a[32];
#pragma unroll
            for (int i = 0; i < 32; i++) a[i] = unpack_sum(acc[i]);
            recA = merge32(a, l);
#pragma unroll
            for (int i = 0; i < 32; i++) a[i] = unpack_sum(acc[32 + i]);
            recB = merge32(a, l);
        }
        if (tid >= 128) {
            sP[cellA] = recA;
            sP[cellA + 64] = recB;
        }
        __syncthreads();

        if (!zf) {
            if (tid < 128) {
                // ---- update 2 cells ----
                float rtA = sP[cellA] + recA;
                float rtB = sP[cellA + 64] + recB;
                float inxA = 0.f, inxB = 0.f;
#pragma unroll
                for (int i = 0; i < NIN; i++) {
                    float xv = sXc[bA * 8 + i];
                    inxA = fmaf(xv, sWi[jA * 8 + i], inxA);
                    inxB = fmaf(xv, sWi[(jA + 4) * 8 + i], inxB);
                }
                float rsA = fmaf(-BETAC * rA, hTA, (1.0f - rA) * itauA);
                float rNA = fmaf(rsA, DTC, rA);
                float hNA = fmaf(rtA + inxA - hA, 0.1f, hA);
                float hTNA = my_tanh(hNA);
                float rsB = fmaf(-BETAC * rB, hTB, (1.0f - rB) * itauB);
                float rNB = fmaf(rsB, DTC, rB);
                float hNB = fmaf(rtB + inxB - hB, 0.1f, hB);
                float hTNB = my_tanh(hNB);

                __stcg(&g_v[nb][bA * Hdim + jrow + jA], rNA * hTNA);
                __stcg(&g_v[nb][bA * Hdim + jrow + jA + 4], rNB * hTNB);
                sHT[cellA] = hTNA;
                sHT[cellA + 64] = hTNB;
                asm volatile("bar.sync 1,128;" ::: "memory");
                if (tid == 0) { fence_gpu(); red_add(&g_wcnt[myg * PAD]); }

                size_t oiA = ((size_t)bA * Tdim + t) * Hdim + jrow + jA;
                stcs(&out_h[oiA], hNA);
                stcs(&out_r[oiA], rNA);
                stcs(&out_h[oiA + 4], hNB);
                stcs(&out_r[oiA + 4], rNB);
                hA = hNA; rA = rNA; hTA = hTNA;
                hB = hNB; rB = rNB; hTB = hTNB;

                // z partial (off critical path)
                int bb2 = tid >> 3, oo = tid & 7;
                float s = 0.f;
#pragma unroll
                for (int j2 = 0; j2 < RPC; j2++) s = fmaf(sHT[j2 * 16 + bb2], sWo[oo * 16 + j2], s);
                stcs(&g_zt[(size_t)t * (NCTA * 128) + cta * 128 + tid], s);
            } else if (t + 1 < Tdim) {
                // ---- kg1: next-step head (overlaps kg0 update) ----
                const unsigned tg2 = tgt + 32u;
                if (w == 4) {
                    const unsigned* cp = &g_wcnt[((myg + l) & 3) * PAD];
                    bool pass = (l >= 4);
                    unsigned ball;
                    do {
                        if (l < 4 && !pass) pass = (ldrelax(cp) >= tg2);
                        ball = __ballot_sync(0xffffffffu, pass);
                    } while (!(ball & 1u));
                    if (l < 4 && pass) {
                        while (ldacq(cp) < tg2) {}
                        st_flag(smaddr(&sFlag[(myg + l) & 3]), stamp + 1u);
                    }
                    __syncwarp();
                }
                while (ld_flag(fa0) < stamp + 1u) {}
                prefetch128(sV, g_v[nb], 0, c0, tid - 128);
                int t128 = tid - 128;
                sX[nb * 128 + t128] =
                    x[((size_t)(t128 >> 3) * Tdim + (t + 1)) * NIN + (t128 & 7)];
            }
        } else {
            // ---- zf fallback tail (correctness path) ----
            if (tid < 128) {
                float rtA = sP[cellA] + recA;
                float rtB = sP[cellA + 64] + recB;
                float inxA = 0.f, inxB = 0.f, ztA = 0.f, ztB = 0.f;
#pragma unroll
                for (int i = 0; i < NIN; i++) {
                    float xv = sXc[bA * 8 + i];
                    inxA = fmaf(xv, sWi[jA * 8 + i], inxA);
                    inxB = fmaf(xv, sWi[(jA + 4) * 8 + i], inxB);
                }
#pragma unroll
                for (int o = 0; o < NOUT; o++) {
                    float zv = sZ[bA * 8 + o];
                    ztA = fmaf(zv, sWz[jA * 8 + o], ztA);
                    ztB = fmaf(zv, sWz[(jA + 4) * 8 + o], ztB);
                }
                float rsA = fmaf(-BETAC * rA, hTA, (1.0f - rA) * itauA);
                float rNA = fmaf(rsA, DTC, rA);
                float hNA = fmaf(rtA + inxA + ztA - hA, 0.1f, hA);
                float hTNA = my_tanh(hNA);
                float rsB = fmaf(-BETAC * rB, hTB, (1.0f - rB) * itauB);
                float rNB = fmaf(rsB, DTC, rB);
                float hNB = fmaf(rtB + inxB + ztB - hB, 0.1f, hB);
                float hTNB = my_tanh(hNB);

                __stcg(&g_v[nb][bA * Hdim + jrow + jA], rNA * hTNA);
                __stcg(&g_v[nb][bA * Hdim + jrow + jA + 4], rNB * hTNB);
                sHT[cellA] = hTNA;
                sHT[cellA + 64] = hTNB;
                size_t oiA = ((size_t)bA * Tdim + t) * Hdim + jrow + jA;
                stcs(&out_h[oiA], hNA);
                stcs(&out_r[oiA], rNA);
                stcs(&out_h[oiA + 4], hNB);
                stcs(&out_r[oiA + 4], rNB);
                hA = hNA; rA = rNA; hTA = hTNA;
                hB = hNB; rB = rNB; hTB = hTNB;
            }
            __syncthreads();
            if (tid == 0) { fence_gpu(); red_add(&g_wcnt[myg * PAD]); }
            if (tid < 128) {
                int bb2 = tid >> 3, oo = tid & 7;
                float s = 0.f;
#pragma unroll
                for (int j2 = 0; j2 < RPC; j2++) s = fmaf(sHT[j2 * 16 + bb2], sWo[oo * 16 + j2], s);
                __stcg(&g_zt[(size_t)t * (NCTA * 128) + cta * 128 + tid], s);
            }
            __syncthreads();
            if (tid == 0) { fence_gpu(); red_add(&g_zcnt[0]); }
            if (t + 1 < Tdim) {
                const unsigned tg2 = tgt + 32u;
                if (w == 4) {
                    const unsigned* cp = &g_wcnt[((myg + l) & 3) * PAD];
                    bool pass = (l >= 4);
                    unsigned ball;
                    do {
                        if (l < 4 && !pass) pass = (ldrelax(cp) >= tg2);
                        ball = __ballot_sync(0xffffffffu, pass);
                    } while (!(ball & 1u));
                    if (l < 4 && pass) {
                        while (ldacq(cp) < tg2) {}
                        st_flag(smaddr(&sFlag[(myg + l) & 3]), stamp + 1u);
                    }
                    __syncwarp();
                }
                __syncthreads();
                if (tid >= 128) {
                    while (ld_flag(fa0) < stamp + 1u) {}
                    prefetch128(sV, g_v[nb], 0, c0, tid - 128);
                    int t128 = tid - 128;
                    sX[nb * 128 + t128] =
                        x[((size_t)(t128 >> 3) * Tdim + (t + 1)) * NIN + (t128 & 7)];
                }
            }
        }
    }
}

extern "C" void kernel_launch(void* const* d_in, const int* in_sizes, int n_in,
                              void* d_out, int out_size) {
    const float* x   = (const float*)d_in[0];
    const float* h0  = (const float*)d_in[1];
    const float* Wih = (const float*)d_in[2];
    const float* Wt  = (const float*)d_in[3];
    const float* Wf  = (const float*)d_in[4];
    const float* mk  = (const float*)d_in[5];
    const float* Whz = (const float*)d_in[6];
    const float* Wzh = (const float*)d_in[7];
    const float* tau = (const float*)d_in[8];
    float* out = (float*)d_out;

    reset_counters<<<1, 256>>>();
    scan_wzh<<<(Hdim * NOUT + 255) / 256, 256>>>(Wzh);
    build_wm<<<(Hdim * Hdim + 255) / 256, 256>>>(Wt, Wf, mk);

    cudaFuncSetAttribute(rnn_persist, cudaFuncAttributeMaxDynamicSharedMemorySize, 50452 * 4);
    rnn_persist<<<NCTA, NTH, 50452 * 4>>>(x, h0, Wih, Whz, Wzh, tau, out);

    zred<<<(Tdim * 128) / 256, 256>>>(out);
}